// round 9
// baseline (speedup 1.0000x reference)
#include <cuda_runtime.h>
#include <cuda_bf16.h>
#include <cstdint>

#define NN   10000
#define EE   320000
#define ET   (EE + NN)
#define DIN  128
#define DOUT 256
#define MT   79            // ceil(10000/128)
#define NPAD (MT * 128)
#define MAXC 1024
#define NTRI (MT * (MT + 1) / 2)   // 3160 upper-triangle tiles

// ---------------- scratch (device globals; no allocations allowed) ----------
__device__ __nv_bfloat16  g_h16[(size_t)NN * DOUT];   // h = x@W (bf16)
__device__ __nv_bfloat16  g_hb[(size_t)NPAD * DOUT];  // bf16 y (pad rows stay 0)
__device__ float          g_asrc[NN];
__device__ float          g_adst[NN];
__device__ int            g_cnt[NN];
__device__ int            g_cur[NN];
__device__ int            g_off[NN + 1];
__device__ int            g_csr[ET];
__device__ float          g_ss;

__device__ __forceinline__ uint32_t smem_u32(const void* p) {
    uint32_t a;
    asm("{ .reg .u64 t; cvta.to.shared.u64 t, %1; cvt.u32.u64 %0, t; }"
        : "=r"(a) : "l"(p));
    return a;
}
#define CP16(dst, src) \
    asm volatile("cp.async.cg.shared.global [%0], [%1], 16;" :: "r"(dst), "l"(src))
#define CP_COMMIT() asm volatile("cp.async.commit_group;" ::: "memory")
#define CP_WAIT(n)  asm volatile("cp.async.wait_group %0;" :: "n"(n) : "memory")

__device__ __forceinline__ void ldsm4(uint32_t& r0, uint32_t& r1,
                                      uint32_t& r2, uint32_t& r3, uint32_t a) {
    asm volatile("ldmatrix.sync.aligned.m8n8.x4.shared.b16 {%0,%1,%2,%3}, [%4];"
                 : "=r"(r0), "=r"(r1), "=r"(r2), "=r"(r3) : "r"(a));
}
__device__ __forceinline__ void ldsm4t(uint32_t& r0, uint32_t& r1,
                                       uint32_t& r2, uint32_t& r3, uint32_t a) {
    asm volatile("ldmatrix.sync.aligned.m8n8.x4.trans.shared.b16 {%0,%1,%2,%3}, [%4];"
                 : "=r"(r0), "=r"(r1), "=r"(r2), "=r"(r3) : "r"(a));
}
__device__ __forceinline__ void mma16816(float* c, const uint32_t* a,
                                         const uint32_t* b) {
    asm volatile(
        "mma.sync.aligned.m16n8k16.row.col.f32.bf16.bf16.f32 "
        "{%0,%1,%2,%3}, {%4,%5,%6,%7}, {%8,%9}, {%0,%1,%2,%3};"
        : "+f"(c[0]), "+f"(c[1]), "+f"(c[2]), "+f"(c[3])
        : "r"(a[0]), "r"(a[1]), "r"(a[2]), "r"(a[3]), "r"(b[0]), "r"(b[1]));
}

// ---------------- K1: h = x@W via mma.sync (bf16 in/fp32 accum) --------------
// Grid 158: bm = blk>>1 (row tile), nh = blk&1 (128-col half of DOUT).
static constexpr int SMEM_HMM = 2 * 32768;   // sX 32KB + sW 32KB

__global__ void __launch_bounds__(256) k_hmm(const float* __restrict__ x,
                                             const float* __restrict__ W) {
    extern __shared__ char smem[];
    char* sX = smem;
    char* sW = smem + 32768;
    const int tid = threadIdx.x, wid = tid >> 5, lane = tid & 31;
    const int warp_m = wid >> 1, warp_n = wid & 1;
    const int bm = blockIdx.x >> 1, nh = blockIdx.x & 1;

    // stage x[bm*128 .. +128][0..128) and W[0..128)[nh*128 .. +128) as bf16
#pragma unroll
    for (int it = 0; it < 8; it++) {
        int idx = it * 256 + tid;
        int lr = idx >> 4, c = idx & 15;
        uint32_t so = (uint32_t)(lr * 256 + (c ^ (lr & 7)) * 16);
        // x tile
        int r = bm * 128 + lr;
        float4 v0, v1;
        if (r < NN) {
            const float4* xp = (const float4*)(x + (size_t)r * DIN + c * 8);
            v0 = xp[0]; v1 = xp[1];
        } else {
            v0 = make_float4(0.f, 0.f, 0.f, 0.f); v1 = v0;
        }
        uint32_t p[4];
        p[0] = *(uint32_t*)&(__nv_bfloat162&)*(__nv_bfloat162*)&p[0]; // placeholder
        __nv_bfloat162 b0 = __floats2bfloat162_rn(v0.x, v0.y);
        __nv_bfloat162 b1 = __floats2bfloat162_rn(v0.z, v0.w);
        __nv_bfloat162 b2 = __floats2bfloat162_rn(v1.x, v1.y);
        __nv_bfloat162 b3 = __floats2bfloat162_rn(v1.z, v1.w);
        p[0] = *(uint32_t*)&b0; p[1] = *(uint32_t*)&b1;
        p[2] = *(uint32_t*)&b2; p[3] = *(uint32_t*)&b3;
        *(uint4*)(sX + so) = *(uint4*)p;
        // W tile (row = k, 128 bf16 per row)
        const float4* wp = (const float4*)(W + (size_t)lr * DOUT + nh * 128 + c * 8);
        v0 = wp[0]; v1 = wp[1];
        b0 = __floats2bfloat162_rn(v0.x, v0.y);
        b1 = __floats2bfloat162_rn(v0.z, v0.w);
        b2 = __floats2bfloat162_rn(v1.x, v1.y);
        b3 = __floats2bfloat162_rn(v1.z, v1.w);
        p[0] = *(uint32_t*)&b0; p[1] = *(uint32_t*)&b1;
        p[2] = *(uint32_t*)&b2; p[3] = *(uint32_t*)&b3;
        *(uint4*)(sW + so) = *(uint4*)p;
    }
    __syncthreads();

    uint32_t aBase = smem_u32(sX), bBase = smem_u32(sW);
    int arow0 = warp_m * 32 + (lane & 15);
    int akh   = lane >> 4;
    int bkr_in = lane & 15;
    int bch_off = lane >> 4;

    float acc[2][8][4];
#pragma unroll
    for (int i = 0; i < 2; i++)
#pragma unroll
        for (int j = 0; j < 8; j++)
#pragma unroll
            for (int q = 0; q < 4; q++) acc[i][j][q] = 0.f;

#pragma unroll
    for (int ks = 0; ks < 8; ks++) {
        uint32_t afr[2][4];
#pragma unroll
        for (int mt = 0; mt < 2; mt++) {
            int r = arow0 + mt * 16;
            int ch = (ks * 2 + akh) ^ (r & 7);
            ldsm4(afr[mt][0], afr[mt][1], afr[mt][2], afr[mt][3],
                  aBase + r * 256 + ch * 16);
        }
        uint32_t bfr[8][2];
        int kr = ks * 16 + bkr_in;
#pragma unroll
        for (int t = 0; t < 4; t++) {
            int c = warp_n * 8 + 2 * t + bch_off;
            int cs = c ^ (kr & 7);
            uint32_t q0, q1, q2, q3;
            ldsm4t(q0, q1, q2, q3, bBase + kr * 256 + cs * 16);
            bfr[2 * t][0] = q0; bfr[2 * t][1] = q1;
            bfr[2 * t + 1][0] = q2; bfr[2 * t + 1][1] = q3;
        }
#pragma unroll
        for (int mt = 0; mt < 2; mt++)
#pragma unroll
            for (int nt = 0; nt < 8; nt++)
                mma16816(acc[mt][nt], afr[mt], bfr[nt]);
    }

    // store bf16x2 pairs to g_h16
    const int g = lane >> 2, tig = lane & 3;
#pragma unroll
    for (int mt = 0; mt < 2; mt++) {
#pragma unroll
        for (int nt = 0; nt < 8; nt++) {
            int row0 = bm * 128 + warp_m * 32 + mt * 16 + g;
            int col = nh * 128 + warp_n * 64 + nt * 8 + tig * 2;
            float* c = acc[mt][nt];
            if (row0 < NN) {
                __nv_bfloat162 b = __floats2bfloat162_rn(c[0], c[1]);
                *(uint32_t*)(g_h16 + (size_t)row0 * DOUT + col) = *(uint32_t*)&b;
            }
            if (row0 + 8 < NN) {
                __nv_bfloat162 b = __floats2bfloat162_rn(c[2], c[3]);
                *(uint32_t*)(g_h16 + (size_t)(row0 + 8) * DOUT + col) = *(uint32_t*)&b;
            }
        }
    }
}

// ---------------- K1b: attention logits from bf16 h --------------------------
__global__ void __launch_bounds__(256) k_logit(const float* __restrict__ att_s,
                                               const float* __restrict__ att_d) {
    __shared__ float ss[DOUT], sd[DOUT];
    const int tid = threadIdx.x, lane = tid & 31, w = tid >> 5;
    ss[tid] = att_s[tid];
    sd[tid] = att_d[tid];
    __syncthreads();
    int row = blockIdx.x * 8 + w;
    if (row >= NN) return;
    const uint4* hp = (const uint4*)(g_h16 + (size_t)row * DOUT);
    uint4 v = hp[lane];
    float ps = 0.f, pd = 0.f;
    const __nv_bfloat162* hv = (const __nv_bfloat162*)&v;
#pragma unroll
    for (int j = 0; j < 4; j++) {
        float2 f = __bfloat1622float2(hv[j]);
        int c = lane * 8 + j * 2;
        ps = fmaf(f.x, ss[c], ps);     pd = fmaf(f.x, sd[c], pd);
        ps = fmaf(f.y, ss[c + 1], ps); pd = fmaf(f.y, sd[c + 1], pd);
    }
#pragma unroll
    for (int o = 16; o; o >>= 1) {
        ps += __shfl_down_sync(0xffffffffu, ps, o);
        pd += __shfl_down_sync(0xffffffffu, pd, o);
    }
    if (lane == 0) { g_asrc[row] = ps; g_adst[row] = pd; }
}

// ---------------- K2: CSR build — count / scan(+self-clean) / fill ----------
__global__ void k_count(const int* __restrict__ ei) {
    int e = blockIdx.x * 256 + threadIdx.x;
    if (e >= ET) return;
    int d = (e < EE) ? ei[EE + e] : (e - EE);
    atomicAdd(&g_cnt[d], 1);
}

__global__ void __launch_bounds__(1024) k_scan() {
    __shared__ int wsum[32];
    const int tid = threadIdx.x, lane = tid & 31, w = tid >> 5;
    const int base = tid * 10;
    int v[10], s = 0;
#pragma unroll
    for (int j = 0; j < 10; j++) {
        int i = base + j;
        v[j] = (i < NN) ? g_cnt[i] : 0;
        s += v[j];
    }
    int xs = s;
#pragma unroll
    for (int o = 1; o < 32; o <<= 1) {
        int y = __shfl_up_sync(0xffffffffu, xs, o);
        if (lane >= o) xs += y;
    }
    if (lane == 31) wsum[w] = xs;
    __syncthreads();
    if (w == 0) {
        int t2 = wsum[lane];
#pragma unroll
        for (int o = 1; o < 32; o <<= 1) {
            int y = __shfl_up_sync(0xffffffffu, t2, o);
            if (lane >= o) t2 += y;
        }
        wsum[lane] = t2;
    }
    __syncthreads();
    int run = xs - s + (w ? wsum[w - 1] : 0);
#pragma unroll
    for (int j = 0; j < 10; j++) {
        run += v[j];
        int i = base + j;
        if (i < NN) {
            g_off[i + 1] = run;
            g_cnt[i] = 0;          // self-clean for next graph replay
            g_cur[i] = 0;
        }
    }
    if (tid == 0) { g_off[0] = 0; g_ss = 0.f; }
}

__global__ void k_fill(const int* __restrict__ ei) {
    int e = blockIdx.x * 256 + threadIdx.x;
    if (e >= ET) return;
    int s, d;
    if (e < EE) { s = ei[e]; d = ei[EE + e]; } else { s = d = e - EE; }
    int pos = atomicAdd(&g_cur[d], 1);
    g_csr[g_off[d] + pos] = s;
}

// ---------------- K3: fused GAT row — softmax + gather-agg + bias/leaky ------
__global__ void __launch_bounds__(256) k_agg(const float* __restrict__ bias) {
    __shared__ int   ssrc[MAXC];
    __shared__ float sal[MAXC];
    __shared__ float red[8];
    __shared__ float s_amax, s_denom;
    const int d = blockIdx.x, tid = threadIdx.x, lane = tid & 31, w = tid >> 5;
    const int o0 = g_off[d];
    const int deg = g_off[d + 1] - o0;
    const float adst = g_adst[d];

    float mx = -3.0e38f;
    for (int i = tid; i < deg; i += 256) {
        int s = g_csr[o0 + i];
        float a = g_asrc[s] + adst;
        a = a > 0.f ? a : 0.2f * a;
        if (i < MAXC) { ssrc[i] = s; sal[i] = a; }
        mx = fmaxf(mx, a);
    }
#pragma unroll
    for (int o = 16; o; o >>= 1) mx = fmaxf(mx, __shfl_xor_sync(0xffffffffu, mx, o));
    if (lane == 0) red[w] = mx;
    __syncthreads();
    if (tid == 0) {
        float m = red[0];
#pragma unroll
        for (int j = 1; j < 8; j++) m = fmaxf(m, red[j]);
        s_amax = m;
    }
    __syncthreads();
    const float amax = s_amax;

    float sum = 0.f;
    for (int i = tid; i < deg; i += 256) {
        float a;
        if (i < MAXC) a = sal[i];
        else {
            int s = g_csr[o0 + i];
            a = g_asrc[s] + adst;
            a = a > 0.f ? a : 0.2f * a;
        }
        float ex = __expf(a - amax);
        if (i < MAXC) sal[i] = ex;
        sum += ex;
    }
#pragma unroll
    for (int o = 16; o; o >>= 1) sum += __shfl_xor_sync(0xffffffffu, sum, o);
    if (lane == 0) red[w] = sum;
    __syncthreads();
    if (tid == 0) {
        float s2 = 0.f;
#pragma unroll
        for (int j = 0; j < 8; j++) s2 += red[j];
        s_denom = s2;
    }
    __syncthreads();
    const float cs = 1.f / (s_denom + 1e-16f);

    float acc = 0.f;
#pragma unroll 4
    for (int i = 0; i < deg; i++) {
        float ex; int s;
        if (i < MAXC) { ex = sal[i]; s = ssrc[i]; }
        else {
            s = g_csr[o0 + i];
            float a = g_asrc[s] + adst;
            a = a > 0.f ? a : 0.2f * a;
            ex = __expf(a - amax);
        }
        acc += ex * __bfloat162float(g_h16[(size_t)s * DOUT + tid]);
    }
    float y = fmaf(acc, cs, bias[tid]);
    y = y > 0.f ? y : 0.02f * y;
    g_hb[(size_t)d * DOUT + tid] = __float2bfloat16(y);

    float p = y * y;
#pragma unroll
    for (int o = 16; o; o >>= 1) p += __shfl_xor_sync(0xffffffffu, p, o);
    if (lane == 0) red[w] = p;
    __syncthreads();
    if (tid == 0) {
        float s2 = 0.f;
#pragma unroll
        for (int j = 0; j < 8; j++) s2 += red[j];
        atomicAdd(&g_ss, s2);
    }
}

// ---------------- K4: symmetric GEMM + sigmoid epilogue ---------------------
static constexpr int TILE_BYTES = 128 * 512;
static constexpr int SMEM_GEMM  = 2 * TILE_BYTES;     // 128 KB
static constexpr int TSTRIDE    = 132;

__device__ __forceinline__ float sigf(float z) {
    float t;
    asm("tanh.approx.f32 %0, %1;" : "=f"(t) : "f"(z * 0.5f));
    return fmaf(t, 0.5f, 0.5f);
}
__device__ __forceinline__ int rowstart(int m) {
    return m * MT - ((m * (m - 1)) >> 1);
}

__global__ void __launch_bounds__(256, 1) k_gemm(float* __restrict__ out) {
    int t = blockIdx.x;
    int bm = (int)(((2.0f * MT + 1.0f) -
                    sqrtf((2.0f * MT + 1.0f) * (2.0f * MT + 1.0f) - 8.0f * (float)t)) * 0.5f);
    if (bm > 0 && rowstart(bm) > t) bm--;
    while (rowstart(bm + 1) <= t) bm++;
    const int bn = bm + (t - rowstart(bm));

    extern __shared__ char smem[];
    char* sA = smem;
    char* sB = smem + TILE_BYTES;
    const int tid = threadIdx.x, wid = tid >> 5, lane = tid & 31;
    const int warp_m = wid >> 1, warp_n = wid & 1;
    const bool diag = (bm == bn);

    const char* gA = (const char*)(g_hb + (size_t)bm * 128 * DOUT);
    const char* gB = (const char*)(g_hb + (size_t)bn * 128 * DOUT);
    uint32_t aS = smem_u32(sA), bS = smem_u32(sB);
#pragma unroll
    for (int half = 0; half < 2; half++) {
#pragma unroll
        for (int it = 0; it < 8; it++) {
            int idx = it * 256 + tid;
            int r = idx >> 4, c = (idx & 15) + half * 16;
            uint32_t so = (uint32_t)(r * 512 + (c ^ (r & 7)) * 16);
            uint32_t go = (uint32_t)(r * 512 + c * 16);
            CP16(aS + so, gA + go);
            if (!diag) CP16(bS + so, gB + go);
        }
        CP_COMMIT();
    }
    uint32_t aBase = aS;
    uint32_t bBase = diag ? aS : bS;

    int arow0 = warp_m * 32 + (lane & 15);
    int akh   = lane >> 4;
    int bm4   = lane >> 3;
    int brow_in = lane & 7;
    int bkh   = bm4 & 1;
    int bnt_off = bm4 >> 1;

    float acc[2][8][4];
#pragma unroll
    for (int i = 0; i < 2; i++)
#pragma unroll
        for (int j = 0; j < 8; j++)
#pragma unroll
            for (int q = 0; q < 4; q++) acc[i][j][q] = 0.f;

    CP_WAIT(1);
    __syncthreads();

#pragma unroll
    for (int ks = 0; ks < 16; ks++) {
        if (ks == 8) {
            CP_WAIT(0);
            __syncthreads();
        }
        uint32_t afr[2][4];
#pragma unroll
        for (int mt = 0; mt < 2; mt++) {
            int r = arow0 + mt * 16;
            int ch = (ks * 2 + akh) ^ (r & 7);
            ldsm4(afr[mt][0], afr[mt][1], afr[mt][2], afr[mt][3],
                  aBase + r * 512 + ch * 16);
        }
        uint32_t bfr[8][2];
#pragma unroll
        for (int tq = 0; tq < 4; tq++) {
            int nt = 2 * tq + bnt_off;
            int r = warp_n * 64 + nt * 8 + brow_in;
            int ch = (ks * 2 + bkh) ^ (r & 7);
            uint32_t q0, q1, q2, q3;
            ldsm4(q0, q1, q2, q3, bBase + r * 512 + ch * 16);
            bfr[2 * tq][0] = q0; bfr[2 * tq][1] = q1;
            bfr[2 * tq + 1][0] = q2; bfr[2 * tq + 1][1] = q3;
        }
#pragma unroll
        for (int mt = 0; mt < 2; mt++)
#pragma unroll
            for (int nt = 0; nt < 8; nt++)
                mma16816(acc[mt][nt], afr[mt], bfr[nt]);
    }

    const float inv_ss = 1.0f / g_ss;
#pragma unroll
    for (int mt = 0; mt < 2; mt++)
#pragma unroll
        for (int nt = 0; nt < 8; nt++)
#pragma unroll
            for (int q = 0; q < 4; q++)
                acc[mt][nt][q] = sigf(acc[mt][nt][q] * inv_ss);

    const int g = lane >> 2, tig = lane & 3;
#pragma unroll
    for (int mt = 0; mt < 2; mt++) {
#pragma unroll
        for (int nt = 0; nt < 8; nt++) {
            int row0 = bm * 128 + warp_m * 32 + mt * 16 + g;
            int col = bn * 128 + warp_n * 64 + nt * 8 + tig * 2;
            if (col < NN) {
                float* c = acc[mt][nt];
                if (row0 < NN)
                    *(float2*)(out + (size_t)row0 * NN + col) = make_float2(c[0], c[1]);
                if (row0 + 8 < NN)
                    *(float2*)(out + (size_t)(row0 + 8) * NN + col) = make_float2(c[2], c[3]);
            }
        }
    }

    if (!diag) {
        __syncthreads();
        float* sT = (float*)smem;
#pragma unroll
        for (int mt = 0; mt < 2; mt++) {
#pragma unroll
            for (int nt = 0; nt < 8; nt++) {
                int rl = warp_m * 32 + mt * 16 + g;
                int cl = warp_n * 64 + nt * 8 + tig * 2;
                float* c = acc[mt][nt];
                sT[cl * TSTRIDE + rl]           = c[0];
                sT[(cl + 1) * TSTRIDE + rl]     = c[1];
                sT[cl * TSTRIDE + rl + 8]       = c[2];
                sT[(cl + 1) * TSTRIDE + rl + 8] = c[3];
            }
        }
        __syncthreads();
        int c4 = tid & 31;
        int C = bm * 128 + c4 * 4;
        bool cok = (C + 3) < NN;
        for (int mr = tid >> 5; mr < 128; mr += 8) {
            int R = bn * 128 + mr;
            if (R < NN && cok) {
                const float* sp = sT + mr * TSTRIDE + c4 * 4;
                *(float4*)(out + (size_t)R * NN + C) =
                    make_float4(sp[0], sp[1], sp[2], sp[3]);
            }
        }
    }
}

// ---------------- launch ------------------------------------------------------
extern "C" void kernel_launch(void* const* d_in, const int* in_sizes, int n_in,
                              void* d_out, int out_size) {
    const float* x    = (const float*)d_in[0];
    const int*   ei   = (const int*)d_in[1];
    const float* W    = (const float*)d_in[2];
    const float* atts = (const float*)d_in[3];
    const float* attd = (const float*)d_in[4];
    const float* bias = (const float*)d_in[5];
    float* out = (float*)d_out;

    static cudaStream_t s1 = nullptr;
    static cudaEvent_t evf = nullptr, evj = nullptr;
    if (!s1) {
        cudaStreamCreateWithFlags(&s1, cudaStreamNonBlocking);
        cudaEventCreateWithFlags(&evf, cudaEventDisableTiming);
        cudaEventCreateWithFlags(&evj, cudaEventDisableTiming);
        cudaFuncSetAttribute(k_gemm, cudaFuncAttributeMaxDynamicSharedMemorySize, SMEM_GEMM);
        cudaFuncSetAttribute(k_hmm, cudaFuncAttributeMaxDynamicSharedMemorySize, SMEM_HMM);
    }

    // fork: h-chain on s1 concurrent with CSR chain on the capture stream
    cudaEventRecord(evf, 0);
    cudaStreamWaitEvent(s1, evf, 0);
    k_hmm<<<2 * MT, 256, SMEM_HMM, s1>>>(x, W);
    k_logit<<<(NN + 7) / 8, 256, 0, s1>>>(atts, attd);
    cudaEventRecord(evj, s1);

    k_count<<<(ET + 255) / 256, 256>>>(ei);
    k_scan<<<1, 1024>>>();
    k_fill<<<(ET + 255) / 256, 256>>>(ei);

    cudaStreamWaitEvent(0, evj, 0);
    k_agg<<<NN, 256>>>(bias);
    k_gemm<<<NTRI, 256, SMEM_GEMM>>>(out);
}

// round 10
// speedup vs baseline: 1.1197x; 1.1197x over previous
#include <cuda_runtime.h>
#include <cuda_bf16.h>
#include <cstdint>

#define NN   10000
#define EE   320000
#define ET   (EE + NN)
#define DIN  128
#define DOUT 256
#define MT   79            // ceil(10000/128)
#define NPAD (MT * 128)
#define MAXC 1024
#define NTRI (MT * (MT + 1) / 2)   // 3160 upper-triangle tiles

// ---------------- scratch (device globals; no allocations allowed) ----------
__device__ __nv_bfloat16  g_h16[(size_t)NN * DOUT];   // h = x@W (bf16)
__device__ __nv_bfloat16  g_hb[(size_t)NPAD * DOUT];  // bf16 y (pad rows stay 0)
__device__ float          g_asrc[NN];
__device__ float          g_adst[NN];
__device__ int            g_cnt[NN];
__device__ int            g_cur[NN];
__device__ int            g_off[NN + 1];
__device__ int            g_csr[ET];
__device__ float          g_ss;

__device__ __forceinline__ uint32_t smem_u32(const void* p) {
    uint32_t a;
    asm("{ .reg .u64 t; cvta.to.shared.u64 t, %1; cvt.u32.u64 %0, t; }"
        : "=r"(a) : "l"(p));
    return a;
}
#define CP16(dst, src) \
    asm volatile("cp.async.cg.shared.global [%0], [%1], 16;" :: "r"(dst), "l"(src))
#define CP_COMMIT() asm volatile("cp.async.commit_group;" ::: "memory")
#define CP_WAIT(n)  asm volatile("cp.async.wait_group %0;" :: "n"(n) : "memory")

__device__ __forceinline__ void ldsm4(uint32_t& r0, uint32_t& r1,
                                      uint32_t& r2, uint32_t& r3, uint32_t a) {
    asm volatile("ldmatrix.sync.aligned.m8n8.x4.shared.b16 {%0,%1,%2,%3}, [%4];"
                 : "=r"(r0), "=r"(r1), "=r"(r2), "=r"(r3) : "r"(a));
}
__device__ __forceinline__ void ldsm4t(uint32_t& r0, uint32_t& r1,
                                       uint32_t& r2, uint32_t& r3, uint32_t a) {
    asm volatile("ldmatrix.sync.aligned.m8n8.x4.trans.shared.b16 {%0,%1,%2,%3}, [%4];"
                 : "=r"(r0), "=r"(r1), "=r"(r2), "=r"(r3) : "r"(a));
}
__device__ __forceinline__ void mma16816(float* c, const uint32_t* a,
                                         const uint32_t* b) {
    asm volatile(
        "mma.sync.aligned.m16n8k16.row.col.f32.bf16.bf16.f32 "
        "{%0,%1,%2,%3}, {%4,%5,%6,%7}, {%8,%9}, {%0,%1,%2,%3};"
        : "+f"(c[0]), "+f"(c[1]), "+f"(c[2]), "+f"(c[3])
        : "r"(a[0]), "r"(a[1]), "r"(a[2]), "r"(a[3]), "r"(b[0]), "r"(b[1]));
}

// ---------------- K1: h = x@W via mma.sync (bf16 in/fp32 accum) --------------
static constexpr int SMEM_HMM = 2 * 32768;

__global__ void __launch_bounds__(256) k_hmm(const float* __restrict__ x,
                                             const float* __restrict__ W) {
    extern __shared__ char smem[];
    char* sX = smem;
    char* sW = smem + 32768;
    const int tid = threadIdx.x, wid = tid >> 5, lane = tid & 31;
    const int warp_m = wid >> 1, warp_n = wid & 1;
    const int bm = blockIdx.x >> 1, nh = blockIdx.x & 1;

#pragma unroll
    for (int it = 0; it < 8; it++) {
        int idx = it * 256 + tid;
        int lr = idx >> 4, c = idx & 15;
        uint32_t so = (uint32_t)(lr * 256 + (c ^ (lr & 7)) * 16);
        int r = bm * 128 + lr;
        float4 v0, v1;
        if (r < NN) {
            const float4* xp = (const float4*)(x + (size_t)r * DIN + c * 8);
            v0 = xp[0]; v1 = xp[1];
        } else {
            v0 = make_float4(0.f, 0.f, 0.f, 0.f); v1 = v0;
        }
        uint32_t p[4];
        __nv_bfloat162 b0 = __floats2bfloat162_rn(v0.x, v0.y);
        __nv_bfloat162 b1 = __floats2bfloat162_rn(v0.z, v0.w);
        __nv_bfloat162 b2 = __floats2bfloat162_rn(v1.x, v1.y);
        __nv_bfloat162 b3 = __floats2bfloat162_rn(v1.z, v1.w);
        p[0] = *(uint32_t*)&b0; p[1] = *(uint32_t*)&b1;
        p[2] = *(uint32_t*)&b2; p[3] = *(uint32_t*)&b3;
        *(uint4*)(sX + so) = *(uint4*)p;
        const float4* wp = (const float4*)(W + (size_t)lr * DOUT + nh * 128 + c * 8);
        v0 = wp[0]; v1 = wp[1];
        b0 = __floats2bfloat162_rn(v0.x, v0.y);
        b1 = __floats2bfloat162_rn(v0.z, v0.w);
        b2 = __floats2bfloat162_rn(v1.x, v1.y);
        b3 = __floats2bfloat162_rn(v1.z, v1.w);
        p[0] = *(uint32_t*)&b0; p[1] = *(uint32_t*)&b1;
        p[2] = *(uint32_t*)&b2; p[3] = *(uint32_t*)&b3;
        *(uint4*)(sW + so) = *(uint4*)p;
    }
    __syncthreads();

    uint32_t aBase = smem_u32(sX), bBase = smem_u32(sW);
    int arow0 = warp_m * 32 + (lane & 15);
    int akh   = lane >> 4;
    int bkr_in = lane & 15;
    int bch_off = lane >> 4;

    float acc[2][8][4];
#pragma unroll
    for (int i = 0; i < 2; i++)
#pragma unroll
        for (int j = 0; j < 8; j++)
#pragma unroll
            for (int q = 0; q < 4; q++) acc[i][j][q] = 0.f;

#pragma unroll
    for (int ks = 0; ks < 8; ks++) {
        uint32_t afr[2][4];
#pragma unroll
        for (int mt = 0; mt < 2; mt++) {
            int r = arow0 + mt * 16;
            int ch = (ks * 2 + akh) ^ (r & 7);
            ldsm4(afr[mt][0], afr[mt][1], afr[mt][2], afr[mt][3],
                  aBase + r * 256 + ch * 16);
        }
        uint32_t bfr[8][2];
        int kr = ks * 16 + bkr_in;
#pragma unroll
        for (int t = 0; t < 4; t++) {
            int c = warp_n * 8 + 2 * t + bch_off;
            int cs = c ^ (kr & 7);
            uint32_t q0, q1, q2, q3;
            ldsm4t(q0, q1, q2, q3, bBase + kr * 256 + cs * 16);
            bfr[2 * t][0] = q0; bfr[2 * t][1] = q1;
            bfr[2 * t + 1][0] = q2; bfr[2 * t + 1][1] = q3;
        }
#pragma unroll
        for (int mt = 0; mt < 2; mt++)
#pragma unroll
            for (int nt = 0; nt < 8; nt++)
                mma16816(acc[mt][nt], afr[mt], bfr[nt]);
    }

    const int g = lane >> 2, tig = lane & 3;
#pragma unroll
    for (int mt = 0; mt < 2; mt++) {
#pragma unroll
        for (int nt = 0; nt < 8; nt++) {
            int row0 = bm * 128 + warp_m * 32 + mt * 16 + g;
            int col = nh * 128 + warp_n * 64 + nt * 8 + tig * 2;
            float* c = acc[mt][nt];
            if (row0 < NN) {
                __nv_bfloat162 b = __floats2bfloat162_rn(c[0], c[1]);
                *(uint32_t*)(g_h16 + (size_t)row0 * DOUT + col) = *(uint32_t*)&b;
            }
            if (row0 + 8 < NN) {
                __nv_bfloat162 b = __floats2bfloat162_rn(c[2], c[3]);
                *(uint32_t*)(g_h16 + (size_t)(row0 + 8) * DOUT + col) = *(uint32_t*)&b;
            }
        }
    }
}

// ---------------- K1b: attention logits from bf16 h --------------------------
__global__ void __launch_bounds__(256) k_logit(const float* __restrict__ att_s,
                                               const float* __restrict__ att_d) {
    __shared__ float ss[DOUT], sd[DOUT];
    const int tid = threadIdx.x, lane = tid & 31, w = tid >> 5;
    ss[tid] = att_s[tid];
    sd[tid] = att_d[tid];
    __syncthreads();
    int row = blockIdx.x * 8 + w;
    if (row >= NN) return;
    const uint4* hp = (const uint4*)(g_h16 + (size_t)row * DOUT);
    uint4 v = hp[lane];
    float ps = 0.f, pd = 0.f;
    const __nv_bfloat162* hv = (const __nv_bfloat162*)&v;
#pragma unroll
    for (int j = 0; j < 4; j++) {
        float2 f = __bfloat1622float2(hv[j]);
        int c = lane * 8 + j * 2;
        ps = fmaf(f.x, ss[c], ps);     pd = fmaf(f.x, sd[c], pd);
        ps = fmaf(f.y, ss[c + 1], ps); pd = fmaf(f.y, sd[c + 1], pd);
    }
#pragma unroll
    for (int o = 16; o; o >>= 1) {
        ps += __shfl_down_sync(0xffffffffu, ps, o);
        pd += __shfl_down_sync(0xffffffffu, pd, o);
    }
    if (lane == 0) { g_asrc[row] = ps; g_adst[row] = pd; }
}

// ---------------- K2: CSR build — count / scan(+self-clean) / fill ----------
__global__ void k_count(const int* __restrict__ ei) {
    int e = blockIdx.x * 256 + threadIdx.x;
    if (e >= ET) return;
    int d = (e < EE) ? ei[EE + e] : (e - EE);
    atomicAdd(&g_cnt[d], 1);
}

__global__ void __launch_bounds__(1024) k_scan() {
    __shared__ int wsum[32];
    const int tid = threadIdx.x, lane = tid & 31, w = tid >> 5;
    const int base = tid * 12;
    int v[12], s = 0;
    if (base + 11 < NN) {
        const int4* cp = (const int4*)(g_cnt + base);
        int4 a0 = cp[0], a1 = cp[1], a2 = cp[2];
        v[0] = a0.x; v[1] = a0.y; v[2] = a0.z; v[3] = a0.w;
        v[4] = a1.x; v[5] = a1.y; v[6] = a1.z; v[7] = a1.w;
        v[8] = a2.x; v[9] = a2.y; v[10] = a2.z; v[11] = a2.w;
    } else {
#pragma unroll
        for (int j = 0; j < 12; j++) {
            int i = base + j;
            v[j] = (i < NN) ? g_cnt[i] : 0;
        }
    }
#pragma unroll
    for (int j = 0; j < 12; j++) s += v[j];
    int xs = s;
#pragma unroll
    for (int o = 1; o < 32; o <<= 1) {
        int y = __shfl_up_sync(0xffffffffu, xs, o);
        if (lane >= o) xs += y;
    }
    if (lane == 31) wsum[w] = xs;
    __syncthreads();
    if (w == 0) {
        int t2 = wsum[lane];
#pragma unroll
        for (int o = 1; o < 32; o <<= 1) {
            int y = __shfl_up_sync(0xffffffffu, t2, o);
            if (lane >= o) t2 += y;
        }
        wsum[lane] = t2;
    }
    __syncthreads();
    int run = xs - s + (w ? wsum[w - 1] : 0);
#pragma unroll
    for (int j = 0; j < 12; j++) {
        run += v[j];
        int i = base + j;
        if (i < NN) {
            g_off[i + 1] = run;
            g_cnt[i] = 0;          // self-clean for next graph replay
            g_cur[i] = 0;
        }
    }
    if (tid == 0) { g_off[0] = 0; g_ss = 0.f; }
}

__global__ void k_fill(const int* __restrict__ ei) {
    int e = blockIdx.x * 256 + threadIdx.x;
    if (e >= ET) return;
    int s, d;
    if (e < EE) { s = ei[e]; d = ei[EE + e]; } else { s = d = e - EE; }
    int pos = atomicAdd(&g_cur[d], 1);
    g_csr[g_off[d] + pos] = s;
}

// ---------------- K3: fused GAT row — softmax + gather-agg + bias/leaky ------
__global__ void __launch_bounds__(256) k_agg(const float* __restrict__ bias) {
    __shared__ int   ssrc[MAXC];
    __shared__ float sal[MAXC];
    __shared__ float red[8];
    __shared__ float s_amax, s_denom;
    const int d = blockIdx.x, tid = threadIdx.x, lane = tid & 31, w = tid >> 5;
    const int o0 = g_off[d];
    const int deg = g_off[d + 1] - o0;
    const float adst = g_adst[d];

    float mx = -3.0e38f;
    for (int i = tid; i < deg; i += 256) {
        int s = g_csr[o0 + i];
        float a = g_asrc[s] + adst;
        a = a > 0.f ? a : 0.2f * a;
        if (i < MAXC) { ssrc[i] = s; sal[i] = a; }
        mx = fmaxf(mx, a);
    }
#pragma unroll
    for (int o = 16; o; o >>= 1) mx = fmaxf(mx, __shfl_xor_sync(0xffffffffu, mx, o));
    if (lane == 0) red[w] = mx;
    __syncthreads();
    if (tid == 0) {
        float m = red[0];
#pragma unroll
        for (int j = 1; j < 8; j++) m = fmaxf(m, red[j]);
        s_amax = m;
    }
    __syncthreads();
    const float amax = s_amax;

    float sum = 0.f;
    for (int i = tid; i < deg; i += 256) {
        float a;
        if (i < MAXC) a = sal[i];
        else {
            int s = g_csr[o0 + i];
            a = g_asrc[s] + adst;
            a = a > 0.f ? a : 0.2f * a;
        }
        float ex = __expf(a - amax);
        if (i < MAXC) sal[i] = ex;
        sum += ex;
    }
#pragma unroll
    for (int o = 16; o; o >>= 1) sum += __shfl_xor_sync(0xffffffffu, sum, o);
    if (lane == 0) red[w] = sum;
    __syncthreads();
    if (tid == 0) {
        float s2 = 0.f;
#pragma unroll
        for (int j = 0; j < 8; j++) s2 += red[j];
        s_denom = s2;
    }
    __syncthreads();
    const float cs = 1.f / (s_denom + 1e-16f);

    float acc = 0.f;
#pragma unroll 4
    for (int i = 0; i < deg; i++) {
        float ex; int s;
        if (i < MAXC) { ex = sal[i]; s = ssrc[i]; }
        else {
            s = g_csr[o0 + i];
            float a = g_asrc[s] + adst;
            a = a > 0.f ? a : 0.2f * a;
            ex = __expf(a - amax);
        }
        acc += ex * __bfloat162float(g_h16[(size_t)s * DOUT + tid]);
    }
    float y = fmaf(acc, cs, bias[tid]);
    y = y > 0.f ? y : 0.02f * y;
    g_hb[(size_t)d * DOUT + tid] = __float2bfloat16(y);

    float p = y * y;
#pragma unroll
    for (int o = 16; o; o >>= 1) p += __shfl_xor_sync(0xffffffffu, p, o);
    if (lane == 0) red[w] = p;
    __syncthreads();
    if (tid == 0) {
        float s2 = 0.f;
#pragma unroll
        for (int j = 0; j < 8; j++) s2 += red[j];
        atomicAdd(&g_ss, s2);
    }
}

// ---------------- K4: symmetric GEMM + sigmoid epilogue (occ 2) -------------
// A tile (64 KB) fully staged; B streamed in 4 K64 chunks via 2x16 KB
// ping-pong cp.async. 96 KB smem/CTA -> 2 CTAs/SM: load/epilogue of one CTA
// overlaps the other's HMMA mainloop.
static constexpr int SM_A      = 0;
static constexpr int SM_B0     = 65536;
static constexpr int SM_B1     = 65536 + 16384;
static constexpr int SMEM_GEMM = 96 * 1024;
static constexpr int TSTRIDE   = 132;

__device__ __forceinline__ float sigf(float z) {
    float t;
    asm("tanh.approx.f32 %0, %1;" : "=f"(t) : "f"(z * 0.5f));
    return fmaf(t, 0.5f, 0.5f);
}
__device__ __forceinline__ int rowstart(int m) {
    return m * MT - ((m * (m - 1)) >> 1);
}

__global__ void __launch_bounds__(256, 2) k_gemm(float* __restrict__ out) {
    int t = blockIdx.x;
    int bm = (int)(((2.0f * MT + 1.0f) -
                    sqrtf((2.0f * MT + 1.0f) * (2.0f * MT + 1.0f) - 8.0f * (float)t)) * 0.5f);
    if (bm > 0 && rowstart(bm) > t) bm--;
    while (rowstart(bm + 1) <= t) bm++;
    const int bn = bm + (t - rowstart(bm));

    extern __shared__ char smem[];
    const int tid = threadIdx.x, wid = tid >> 5, lane = tid & 31;
    const int warp_m = wid >> 1, warp_n = wid & 1;
    const bool diag = (bm == bn);

    const char* gA = (const char*)(g_hb + (size_t)bm * 128 * DOUT);
    const char* gB = (const char*)(g_hb + (size_t)bn * 128 * DOUT);
    uint32_t aS = smem_u32(smem);
    const uint32_t bSt[2] = { aS + SM_B0, aS + SM_B1 };

    // prologue: stage A fully + B chunks 0,1 (groups: g0 = A+c0, g1 = c1)
#pragma unroll
    for (int it = 0; it < 16; it++) {
        int idx = it * 256 + tid;
        int r = idx >> 5, c = idx & 31;
        CP16(aS + (uint32_t)(r * 512 + (c ^ (r & 7)) * 16), gA + r * 512 + c * 16);
    }
#pragma unroll
    for (int it = 0; it < 4; it++) {
        int idx = it * 256 + tid;
        int r = idx >> 3, c = idx & 7;
        CP16(bSt[0] + (uint32_t)(r * 128 + (c ^ (r & 7)) * 16),
             gB + r * 512 + c * 16);
    }
    CP_COMMIT();
#pragma unroll
    for (int it = 0; it < 4; it++) {
        int idx = it * 256 + tid;
        int r = idx >> 3, c = idx & 7;
        CP16(bSt[1] + (uint32_t)(r * 128 + (c ^ (r & 7)) * 16),
             gB + r * 512 + 128 + c * 16);
    }
    CP_COMMIT();

    int arow0 = warp_m * 32 + (lane & 15);
    int akh   = lane >> 4;
    int bm4   = lane >> 3;
    int brow_in = lane & 7;
    int bkh   = bm4 & 1;
    int bnt_off = bm4 >> 1;

    float acc[2][8][4];
#pragma unroll
    for (int i = 0; i < 2; i++)
#pragma unroll
        for (int j = 0; j < 8; j++)
#pragma unroll
            for (int q = 0; q < 4; q++) acc[i][j][q] = 0.f;

#pragma unroll
    for (int kc = 0; kc < 4; kc++) {
        if (kc < 3) CP_WAIT(1); else CP_WAIT(0);
        __syncthreads();
        const uint32_t bB = bSt[kc & 1];
#pragma unroll
        for (int kk = 0; kk < 4; kk++) {
            int ks = kc * 4 + kk;
            uint32_t afr[2][4];
#pragma unroll
            for (int mt = 0; mt < 2; mt++) {
                int r = arow0 + mt * 16;
                int ch = (ks * 2 + akh) ^ (r & 7);
                ldsm4(afr[mt][0], afr[mt][1], afr[mt][2], afr[mt][3],
                      aS + r * 512 + ch * 16);
            }
            uint32_t bfr[8][2];
#pragma unroll
            for (int tq = 0; tq < 4; tq++) {
                int nt = 2 * tq + bnt_off;
                int r = warp_n * 64 + nt * 8 + brow_in;
                int kl = (kk * 2 + bkh) ^ (r & 7);
                uint32_t q0, q1, q2, q3;
                ldsm4(q0, q1, q2, q3, bB + r * 128 + kl * 16);
                bfr[2 * tq][0] = q0; bfr[2 * tq][1] = q1;
                bfr[2 * tq + 1][0] = q2; bfr[2 * tq + 1][1] = q3;
            }
#pragma unroll
            for (int mt = 0; mt < 2; mt++)
#pragma unroll
                for (int nt = 0; nt < 8; nt++)
                    mma16816(acc[mt][nt], afr[mt], bfr[nt]);
        }
        if (kc < 2) {
            __syncthreads();      // all warps done with buffer kc&1
#pragma unroll
            for (int it = 0; it < 4; it++) {
                int idx = it * 256 + tid;
                int r = idx >> 3, c = idx & 7;
                CP16(bSt[kc & 1] + (uint32_t)(r * 128 + (c ^ (r & 7)) * 16),
                     gB + r * 512 + (kc + 2) * 128 + c * 16);
            }
            CP_COMMIT();
        }
    }

    const float inv_ss = 1.0f / g_ss;
#pragma unroll
    for (int mt = 0; mt < 2; mt++)
#pragma unroll
        for (int nt = 0; nt < 8; nt++)
#pragma unroll
            for (int q = 0; q < 4; q++)
                acc[mt][nt][q] = sigf(acc[mt][nt][q] * inv_ss);

    const int g = lane >> 2, tig = lane & 3;
#pragma unroll
    for (int mt = 0; mt < 2; mt++) {
#pragma unroll
        for (int nt = 0; nt < 8; nt++) {
            int row0 = bm * 128 + warp_m * 32 + mt * 16 + g;
            int col = bn * 128 + warp_n * 64 + nt * 8 + tig * 2;
            if (col < NN) {
                float* c = acc[mt][nt];
                if (row0 < NN)
                    *(float2*)(out + (size_t)row0 * NN + col) = make_float2(c[0], c[1]);
                if (row0 + 8 < NN)
                    *(float2*)(out + (size_t)(row0 + 8) * NN + col) = make_float2(c[2], c[3]);
            }
        }
    }

    if (!diag) {
        __syncthreads();
        float* sT = (float*)smem;      // 67.6 KB <= 96 KB
#pragma unroll
        for (int mt = 0; mt < 2; mt++) {
#pragma unroll
            for (int nt = 0; nt < 8; nt++) {
                int rl = warp_m * 32 + mt * 16 + g;
                int cl = warp_n * 64 + nt * 8 + tig * 2;
                float* c = acc[mt][nt];
                sT[cl * TSTRIDE + rl]           = c[0];
                sT[(cl + 1) * TSTRIDE + rl]     = c[1];
                sT[cl * TSTRIDE + rl + 8]       = c[2];
                sT[(cl + 1) * TSTRIDE + rl + 8] = c[3];
            }
        }
        __syncthreads();
        int c4 = tid & 31;
        int C = bm * 128 + c4 * 4;
        bool cok = (C + 3) < NN;
        for (int mr = tid >> 5; mr < 128; mr += 8) {
            int R = bn * 128 + mr;
            if (R < NN && cok) {
                const float* sp = sT + mr * TSTRIDE + c4 * 4;
                *(float4*)(out + (size_t)R * NN + C) =
                    make_float4(sp[0], sp[1], sp[2], sp[3]);
            }
        }
    }
}

// ---------------- launch ------------------------------------------------------
extern "C" void kernel_launch(void* const* d_in, const int* in_sizes, int n_in,
                              void* d_out, int out_size) {
    const float* x    = (const float*)d_in[0];
    const int*   ei   = (const int*)d_in[1];
    const float* W    = (const float*)d_in[2];
    const float* atts = (const float*)d_in[3];
    const float* attd = (const float*)d_in[4];
    const float* bias = (const float*)d_in[5];
    float* out = (float*)d_out;

    static cudaStream_t s1 = nullptr;
    static cudaEvent_t evf = nullptr, evj = nullptr;
    if (!s1) {
        cudaStreamCreateWithFlags(&s1, cudaStreamNonBlocking);
        cudaEventCreateWithFlags(&evf, cudaEventDisableTiming);
        cudaEventCreateWithFlags(&evj, cudaEventDisableTiming);
        cudaFuncSetAttribute(k_gemm, cudaFuncAttributeMaxDynamicSharedMemorySize, SMEM_GEMM);
        cudaFuncSetAttribute(k_hmm, cudaFuncAttributeMaxDynamicSharedMemorySize, SMEM_HMM);
    }

    // fork: h-chain on s1 concurrent with CSR chain on the capture stream
    cudaEventRecord(evf, 0);
    cudaStreamWaitEvent(s1, evf, 0);
    k_hmm<<<2 * MT, 256, SMEM_HMM, s1>>>(x, W);
    k_logit<<<(NN + 7) / 8, 256, 0, s1>>>(atts, attd);
    cudaEventRecord(evj, s1);

    k_count<<<(ET + 255) / 256, 256>>>(ei);
    k_scan<<<1, 1024>>>();
    k_fill<<<(ET + 255) / 256, 256>>>(ei);

    cudaStreamWaitEvent(0, evj, 0);
    k_agg<<<NN, 256>>>(bias);
    k_gemm<<<NTRI, 256, SMEM_GEMM>>>(out);
}